// round 5
// baseline (speedup 1.0000x reference)
#include <cuda_runtime.h>
#include <cuda_bf16.h>
#include <cstdint>

// R5: same proven pipeline as R4, retuned for occupancy:
// TC 32->16 (NCH=128), DB 512->256 (NDS=8, 64-thread blocks) => grid 4096
// blocks for K1/K3 (~86% warp occupancy vs 43%), shorter serial FMA chains.

// Problem shapes (fixed by the dataset)
#define BB 4
#define LL 4096
#define MM 2048
#define DD 2048
#define EPSV 1e-4f

#define TC 16              // timesteps per chunk
#define NCH (MM / TC)      // 128 chunks
#define DB 256             // channels per block slice (64 threads x float4)
#define THR (DB / 4)       // 64 threads
#define NDS (DD / DB)      // 8 d-slices

// Input-kind classification
#define K_BYTE 0   // 1-byte bool
#define K_WORD 1   // 4-byte int bool
#define K_FBOOL 2  // float32 0.0/1.0 bool
#define K_PROB 3   // float32 probabilities

// Scratch (static device arrays; no allocation allowed)
__device__ float g_p[BB * MM];
__device__ float g_a[BB * MM];
__device__ int   g_bpos[BB * (MM + 1)];
__device__ float g_A[BB * NCH];
__device__ float g_B[BB * NCH * DD];
__device__ float g_Hin[BB * NCH * DD];

__device__ __forceinline__ void classify(const uint8_t* p, int* kind, int* hz) {
    const uint32_t* w = (const uint32_t*)p;
    bool bb = true, wb = true, fb = true;
    int zb = 0, zw = 0;
    for (int i = 0; i < 64; i++) {
        const uint32_t v = w[i];
        if (v == 0u) zw = 1;
        if (v > 1u) wb = false;
        if (v != 0u && v != 0x3F800000u) fb = false;
#pragma unroll
        for (int k = 0; k < 4; k++) {
            const uint32_t bv = (v >> (8 * k)) & 0xFFu;
            if (bv > 1u) bb = false;
            if (bv == 0u) zb = 1;
        }
    }
    if (wb)      { *kind = K_WORD;  *hz = zw; }
    else if (fb) { *kind = K_FBOOL; *hz = zw; }
    else if (bb) { *kind = K_BYTE;  *hz = zb; }
    else         { *kind = K_PROB;  *hz = 0;  }
}

__device__ __forceinline__ int get_mask(const uint8_t* p, int kind, int l) {
    if (kind == K_BYTE) return p[l] != 0;
    return ((const uint32_t*)p)[l] != 0u;   // K_WORD or K_FBOOL
}

// ---------------------------------------------------------------------------
// K0: identify inputs; per batch: block-scan boundary_mask, gather p, build
// segment table bpos, per-chunk decay products A.
// ---------------------------------------------------------------------------
__global__ void k0_prep(const uint8_t* s0, const uint8_t* s1,
                        const uint8_t* s2, int ns) {
    const int b = blockIdx.x;
    const int tid = threadIdx.x;              // 1024 threads, 4 elems each
    __shared__ int wsum[32];
    __shared__ int s_numB;
    __shared__ int s_pi, s_bi, s_bkind;

    if (tid == 0) {
        const uint8_t* s[3] = { s0, s1, s2 };
        int kind[3], hz[3];
        for (int j = 0; j < ns; j++) classify(s[j], &kind[j], &hz[j]);
        int pi = -1;
        for (int j = 0; j < ns; j++) if (kind[j] == K_PROB) { pi = j; break; }
        if (pi < 0) pi = 0;
        int bi = -1;
        for (int j = 0; j < ns; j++)
            if (j != pi && kind[j] != K_PROB && hz[j]) { bi = j; break; }
        if (bi < 0)
            for (int j = 0; j < ns; j++)
                if (j != pi && kind[j] != K_PROB) { bi = j; break; }
        if (bi < 0) bi = (pi == 1) ? 2 : 1;
        s_pi = pi; s_bi = bi; s_bkind = kind[bi];
    }
    __syncthreads();

    const uint8_t* sel[3] = { s0, s1, s2 };
    const float* prob = (const float*)sel[s_pi];
    const uint8_t* bm = sel[s_bi];
    const int bkind = s_bkind;

    const int l0 = tid * 4;
    int m[4];
    int s = 0;
#pragma unroll
    for (int j = 0; j < 4; j++) {
        m[j] = get_mask(bm, bkind, b * LL + l0 + j);
        s += m[j];
    }

    const int lane = tid & 31, wid = tid >> 5;
    int incl = s;
#pragma unroll
    for (int o = 1; o < 32; o <<= 1) {
        int v = __shfl_up_sync(0xffffffffu, incl, o);
        if (lane >= o) incl += v;
    }
    if (lane == 31) wsum[wid] = incl;
    __syncthreads();
    if (wid == 0) {
        int v = wsum[lane];
#pragma unroll
        for (int o = 1; o < 32; o <<= 1) {
            int u = __shfl_up_sync(0xffffffffu, v, o);
            if (lane >= o) v += u;
        }
        wsum[lane] = v;
        if (lane == 31) s_numB = v;
    }
    __syncthreads();

    const int excl_w = (wid == 0) ? 0 : wsum[wid - 1];
    const int excl_t = excl_w + (incl - s);
    const int numB = s_numB;

    int run = excl_t;
#pragma unroll
    for (int j = 0; j < 4; j++) {
        const int l = l0 + j;
        const int isb = m[j];
        run += isb;
        const int r = isb ? (run - 1) : (numB + (l - run));
        if (r < MM) {
            float p = prob[(size_t)b * LL + l];
            p = fminf(fmaxf(p, EPSV), 1.0f - EPSV);
            g_p[b * MM + r] = p;
            g_a[b * MM + r] = 1.0f - p;
            if (isb) g_bpos[b * (MM + 1) + r] = l;
        }
    }
    for (int r = numB + tid; r <= MM; r += blockDim.x)
        g_bpos[b * (MM + 1) + r] = LL;

    __syncthreads();

    for (int ch = tid; ch < NCH; ch += blockDim.x) {
        float A = 1.0f;
#pragma unroll
        for (int t = 0; t < TC; t++) A *= g_a[b * MM + ch * TC + t];
        g_A[b * NCH + ch] = A;
    }
}

// ---------------------------------------------------------------------------
// K1: chunk-local recurrence with h=0 -> per-chunk carry vectors g_B.
// ---------------------------------------------------------------------------
__global__ void __launch_bounds__(THR)
k1_partials(const float* __restrict__ hid) {
    const int ch = blockIdx.x, ds = blockIdx.y, b = blockIdx.z;
    const int tid = threadIdx.x;

    __shared__ float sp[TC], sa[TC];
    if (tid < TC) {
        sp[tid] = g_p[b * MM + ch * TC + tid];
        sa[tid] = g_a[b * MM + ch * TC + tid];
    }
    __syncthreads();

    const int c0 = ds * DB + tid * 4;
    const float4* src =
        (const float4*)(hid + ((size_t)(b * MM + ch * TC)) * DD + c0);
    const int rs = DD / 4;

    float4 h = make_float4(0.f, 0.f, 0.f, 0.f);
#pragma unroll
    for (int t = 0; t < TC; t++) {
        const float4 x = src[(size_t)t * rs];
        const float p = sp[t], a = sa[t];
        h.x = fmaf(a, h.x, p * x.x);
        h.y = fmaf(a, h.y, p * x.y);
        h.z = fmaf(a, h.z, p * x.z);
        h.w = fmaf(a, h.w, p * x.w);
    }
    *((float4*)&g_B[(size_t)(b * NCH + ch) * DD + c0]) = h;
}

// ---------------------------------------------------------------------------
// K2: sequential combine across the 128 chunks -> exclusive chunk inputs g_Hin.
// ---------------------------------------------------------------------------
__global__ void k2_combine() {
    const int idx = blockIdx.x * blockDim.x + threadIdx.x;   // BB*DD threads
    const int b = idx / DD, d = idx % DD;
    float h = 0.f;
#pragma unroll 4
    for (int c = 0; c < NCH; c++) {
        g_Hin[(size_t)(b * NCH + c) * DD + d] = h;
        h = fmaf(g_A[b * NCH + c], h, g_B[(size_t)(b * NCH + c) * DD + d]);
    }
}

// ---------------------------------------------------------------------------
// K3: chunk-local scan seeded with g_Hin; scatter each state to its
// output segment [bpos[t], bpos[t+1]).
// ---------------------------------------------------------------------------
__global__ void __launch_bounds__(THR)
k3_final(const float* __restrict__ hid, float* __restrict__ out) {
    const int ch = blockIdx.x, ds = blockIdx.y, b = blockIdx.z;
    const int tid = threadIdx.x;

    __shared__ float sp[TC], sa[TC];
    __shared__ int sbp[TC + 1];
    if (tid < TC) {
        sp[tid] = g_p[b * MM + ch * TC + tid];
        sa[tid] = g_a[b * MM + ch * TC + tid];
    }
    if (tid <= TC) sbp[tid] = g_bpos[b * (MM + 1) + ch * TC + tid];
    __syncthreads();

    const int c0 = ds * DB + tid * 4;
    const float4* src =
        (const float4*)(hid + ((size_t)(b * MM + ch * TC)) * DD + c0);
    const int rs = DD / 4;

    float4 h = *((const float4*)&g_Hin[(size_t)(b * NCH + ch) * DD + c0]);
    float4* outbase = (float4*)(out + ((size_t)b * LL) * DD + c0);

#pragma unroll
    for (int t = 0; t < TC; t++) {
        const float4 x = src[(size_t)t * rs];
        const float p = sp[t], a = sa[t];
        h.x = fmaf(a, h.x, p * x.x);
        h.y = fmaf(a, h.y, p * x.y);
        h.z = fmaf(a, h.z, p * x.z);
        h.w = fmaf(a, h.w, p * x.w);
        const int l0 = sbp[t], l1 = sbp[t + 1];
        for (int l = l0; l < l1; l++) outbase[(size_t)l * rs] = h;
    }
}

// ---------------------------------------------------------------------------
extern "C" void kernel_launch(void* const* d_in, const int* in_sizes, int n_in,
                              void* d_out, int out_size) {
    // hidden_states = input with the largest element count (B*M*D = 16.7M)
    int hid_i = 0;
    for (int i = 1; i < n_in; i++)
        if (in_sizes[i] > in_sizes[hid_i]) hid_i = i;
    const float* hid = (const float*)d_in[hid_i];

    // remaining (small) inputs in original order; k0 classifies them on-device
    const void* sm[3] = { nullptr, nullptr, nullptr };
    int ns = 0;
    for (int i = 0; i < n_in && ns < 3; i++)
        if (i != hid_i) sm[ns++] = d_in[i];
    if (ns == 1) { sm[1] = sm[0]; sm[2] = sm[0]; }
    if (ns == 2) { sm[2] = sm[1]; }

    float* out = (float*)d_out;   // (B, L, D) f32

    k0_prep<<<BB, 1024>>>((const uint8_t*)sm[0], (const uint8_t*)sm[1],
                          (const uint8_t*)sm[2], ns);
    dim3 g(NCH, NDS, BB);
    k1_partials<<<g, THR>>>(hid);
    k2_combine<<<(BB * DD) / 256, 256>>>();
    k3_final<<<g, THR>>>(hid, out);
}

// round 8
// speedup vs baseline: 1.0163x; 1.0163x over previous
#include <cuda_runtime.h>
#include <cuda_bf16.h>
#include <cstdint>

// R8: identical to R6/R7 (both infra flakes, never executed on HW).
// cp.async smem staging for K1/K3, unroll-8 K2. TC=16, DB=512, THR=128.

#define BB 4
#define LL 4096
#define MM 2048
#define DD 2048
#define EPSV 1e-4f

#define TC 16              // timesteps per chunk
#define NCH (MM / TC)      // 128 chunks
#define DB 512             // channels per block slice
#define THR 128            // threads per block (1 float4 col each)
#define NDS (DD / DB)      // 4 d-slices

#define K_BYTE 0
#define K_WORD 1
#define K_FBOOL 2
#define K_PROB 3

__device__ float g_p[BB * MM];
__device__ float g_a[BB * MM];
__device__ int   g_bpos[BB * (MM + 1)];
__device__ float g_A[BB * NCH];
__device__ float g_B[BB * NCH * DD];
__device__ float g_Hin[BB * NCH * DD];

__device__ __forceinline__ void cp_async16(void* sdst, const void* gsrc) {
    uint32_t s = (uint32_t)__cvta_generic_to_shared(sdst);
    asm volatile("cp.async.cg.shared.global [%0], [%1], 16;\n"
                 :: "r"(s), "l"(gsrc) : "memory");
}
__device__ __forceinline__ void cp_async_commit_wait() {
    asm volatile("cp.async.commit_group;\n" ::: "memory");
    asm volatile("cp.async.wait_group 0;\n" ::: "memory");
}

__device__ __forceinline__ void classify(const uint8_t* p, int* kind, int* hz) {
    const uint32_t* w = (const uint32_t*)p;
    bool bb = true, wb = true, fb = true;
    int zb = 0, zw = 0;
    for (int i = 0; i < 64; i++) {
        const uint32_t v = w[i];
        if (v == 0u) zw = 1;
        if (v > 1u) wb = false;
        if (v != 0u && v != 0x3F800000u) fb = false;
#pragma unroll
        for (int k = 0; k < 4; k++) {
            const uint32_t bv = (v >> (8 * k)) & 0xFFu;
            if (bv > 1u) bb = false;
            if (bv == 0u) zb = 1;
        }
    }
    if (wb)      { *kind = K_WORD;  *hz = zw; }
    else if (fb) { *kind = K_FBOOL; *hz = zw; }
    else if (bb) { *kind = K_BYTE;  *hz = zb; }
    else         { *kind = K_PROB;  *hz = 0;  }
}

__device__ __forceinline__ int get_mask(const uint8_t* p, int kind, int l) {
    if (kind == K_BYTE) return p[l] != 0;
    return ((const uint32_t*)p)[l] != 0u;
}

// ---------------------------------------------------------------------------
// K0: classify inputs; per batch: scan boundary_mask, gather p, segment table,
// per-chunk decay products A.
// ---------------------------------------------------------------------------
__global__ void k0_prep(const uint8_t* s0, const uint8_t* s1,
                        const uint8_t* s2, int ns) {
    const int b = blockIdx.x;
    const int tid = threadIdx.x;              // 1024 threads, 4 elems each
    __shared__ int wsum[32];
    __shared__ int s_numB;
    __shared__ int s_pi, s_bi, s_bkind;

    if (tid == 0) {
        const uint8_t* s[3] = { s0, s1, s2 };
        int kind[3], hz[3];
        for (int j = 0; j < ns; j++) classify(s[j], &kind[j], &hz[j]);
        int pi = -1;
        for (int j = 0; j < ns; j++) if (kind[j] == K_PROB) { pi = j; break; }
        if (pi < 0) pi = 0;
        int bi = -1;
        for (int j = 0; j < ns; j++)
            if (j != pi && kind[j] != K_PROB && hz[j]) { bi = j; break; }
        if (bi < 0)
            for (int j = 0; j < ns; j++)
                if (j != pi && kind[j] != K_PROB) { bi = j; break; }
        if (bi < 0) bi = (pi == 1) ? 2 : 1;
        s_pi = pi; s_bi = bi; s_bkind = kind[bi];
    }
    __syncthreads();

    const uint8_t* sel[3] = { s0, s1, s2 };
    const float* prob = (const float*)sel[s_pi];
    const uint8_t* bm = sel[s_bi];
    const int bkind = s_bkind;

    const int l0 = tid * 4;
    int m[4];
    int s = 0;
#pragma unroll
    for (int j = 0; j < 4; j++) {
        m[j] = get_mask(bm, bkind, b * LL + l0 + j);
        s += m[j];
    }

    const int lane = tid & 31, wid = tid >> 5;
    int incl = s;
#pragma unroll
    for (int o = 1; o < 32; o <<= 1) {
        int v = __shfl_up_sync(0xffffffffu, incl, o);
        if (lane >= o) incl += v;
    }
    if (lane == 31) wsum[wid] = incl;
    __syncthreads();
    if (wid == 0) {
        int v = wsum[lane];
#pragma unroll
        for (int o = 1; o < 32; o <<= 1) {
            int u = __shfl_up_sync(0xffffffffu, v, o);
            if (lane >= o) v += u;
        }
        wsum[lane] = v;
        if (lane == 31) s_numB = v;
    }
    __syncthreads();

    const int excl_w = (wid == 0) ? 0 : wsum[wid - 1];
    const int excl_t = excl_w + (incl - s);
    const int numB = s_numB;

    int run = excl_t;
#pragma unroll
    for (int j = 0; j < 4; j++) {
        const int l = l0 + j;
        const int isb = m[j];
        run += isb;
        const int r = isb ? (run - 1) : (numB + (l - run));
        if (r < MM) {
            float p = prob[(size_t)b * LL + l];
            p = fminf(fmaxf(p, EPSV), 1.0f - EPSV);
            g_p[b * MM + r] = p;
            g_a[b * MM + r] = 1.0f - p;
            if (isb) g_bpos[b * (MM + 1) + r] = l;
        }
    }
    for (int r = numB + tid; r <= MM; r += blockDim.x)
        g_bpos[b * (MM + 1) + r] = LL;

    __syncthreads();

    for (int ch = tid; ch < NCH; ch += blockDim.x) {
        float A = 1.0f;
#pragma unroll
        for (int t = 0; t < TC; t++) A *= g_a[b * MM + ch * TC + t];
        g_A[b * NCH + ch] = A;
    }
}

// ---------------------------------------------------------------------------
// K1: cp.async-stage the (TC x DB) tile to smem, run chunk-local recurrence
// with h=0 -> per-chunk carry vectors g_B.
// ---------------------------------------------------------------------------
__global__ void __launch_bounds__(THR)
k1_partials(const float* __restrict__ hid) {
    const int ch = blockIdx.x, ds = blockIdx.y, b = blockIdx.z;
    const int tid = threadIdx.x;

    __shared__ float4 tile[TC * THR];          // 32 KB
    __shared__ float sp[TC], sa[TC];
    if (tid < TC) {
        sp[tid] = g_p[b * MM + ch * TC + tid];
        sa[tid] = g_a[b * MM + ch * TC + tid];
    }

    const float4* src =
        (const float4*)(hid + ((size_t)(b * MM + ch * TC)) * DD + ds * DB);
    const int rs = DD / 4;                     // float4 row stride
#pragma unroll
    for (int t = 0; t < TC; t++)
        cp_async16(&tile[t * THR + tid], &src[(size_t)t * rs + tid]);
    cp_async_commit_wait();
    __syncthreads();

    float4 h = make_float4(0.f, 0.f, 0.f, 0.f);
#pragma unroll
    for (int t = 0; t < TC; t++) {
        const float4 x = tile[t * THR + tid];
        const float p = sp[t], a = sa[t];
        h.x = fmaf(a, h.x, p * x.x);
        h.y = fmaf(a, h.y, p * x.y);
        h.z = fmaf(a, h.z, p * x.z);
        h.w = fmaf(a, h.w, p * x.w);
    }
    *((float4*)&g_B[(size_t)(b * NCH + ch) * DD + ds * DB + tid * 4]) = h;
}

// ---------------------------------------------------------------------------
// K2: sequential combine across chunks -> exclusive chunk inputs g_Hin.
// Independent addresses; unroll 8 for MLP (g_B is L2-resident).
// ---------------------------------------------------------------------------
__global__ void k2_combine() {
    const int idx = blockIdx.x * blockDim.x + threadIdx.x;   // BB*DD threads
    const int b = idx / DD, d = idx % DD;
    float h = 0.f;
#pragma unroll 8
    for (int c = 0; c < NCH; c++) {
        g_Hin[(size_t)(b * NCH + c) * DD + d] = h;
        h = fmaf(g_A[b * NCH + c], h, g_B[(size_t)(b * NCH + c) * DD + d]);
    }
}

// ---------------------------------------------------------------------------
// K3: cp.async-stage tile, chunk-local scan seeded with g_Hin, scatter each
// state to its output segment [bpos[t], bpos[t+1]).
// ---------------------------------------------------------------------------
__global__ void __launch_bounds__(THR)
k3_final(const float* __restrict__ hid, float* __restrict__ out) {
    const int ch = blockIdx.x, ds = blockIdx.y, b = blockIdx.z;
    const int tid = threadIdx.x;

    __shared__ float4 tile[TC * THR];          // 32 KB
    __shared__ float sp[TC], sa[TC];
    __shared__ int sbp[TC + 1];
    if (tid < TC) {
        sp[tid] = g_p[b * MM + ch * TC + tid];
        sa[tid] = g_a[b * MM + ch * TC + tid];
    }
    if (tid <= TC) sbp[tid] = g_bpos[b * (MM + 1) + ch * TC + tid];

    const float4* src =
        (const float4*)(hid + ((size_t)(b * MM + ch * TC)) * DD + ds * DB);
    const int rs = DD / 4;
#pragma unroll
    for (int t = 0; t < TC; t++)
        cp_async16(&tile[t * THR + tid], &src[(size_t)t * rs + tid]);

    // overlap: fetch seed while cp.async is in flight
    float4 h = *((const float4*)
                 &g_Hin[(size_t)(b * NCH + ch) * DD + ds * DB + tid * 4]);

    cp_async_commit_wait();
    __syncthreads();

    float4* outbase = (float4*)(out + ((size_t)b * LL) * DD + ds * DB + tid * 4);

#pragma unroll
    for (int t = 0; t < TC; t++) {
        const float4 x = tile[t * THR + tid];
        const float p = sp[t], a = sa[t];
        h.x = fmaf(a, h.x, p * x.x);
        h.y = fmaf(a, h.y, p * x.y);
        h.z = fmaf(a, h.z, p * x.z);
        h.w = fmaf(a, h.w, p * x.w);
        const int l0 = sbp[t], l1 = sbp[t + 1];
        for (int l = l0; l < l1; l++) outbase[(size_t)l * rs] = h;
    }
}

// ---------------------------------------------------------------------------
extern "C" void kernel_launch(void* const* d_in, const int* in_sizes, int n_in,
                              void* d_out, int out_size) {
    // hidden_states = input with the largest element count
    int hid_i = 0;
    for (int i = 1; i < n_in; i++)
        if (in_sizes[i] > in_sizes[hid_i]) hid_i = i;
    const float* hid = (const float*)d_in[hid_i];

    const void* sm[3] = { nullptr, nullptr, nullptr };
    int ns = 0;
    for (int i = 0; i < n_in && ns < 3; i++)
        if (i != hid_i) sm[ns++] = d_in[i];
    if (ns == 1) { sm[1] = sm[0]; sm[2] = sm[0]; }
    if (ns == 2) { sm[2] = sm[1]; }

    float* out = (float*)d_out;

    k0_prep<<<BB, 1024>>>((const uint8_t*)sm[0], (const uint8_t*)sm[1],
                          (const uint8_t*)sm[2], ns);
    dim3 g(NCH, NDS, BB);
    k1_partials<<<g, THR>>>(hid);
    k2_combine<<<(BB * DD) / 256, 256>>>();
    k3_final<<<g, THR>>>(hid, out);
}

// round 9
// speedup vs baseline: 1.4932x; 1.4692x over previous
#include <cuda_runtime.h>
#include <cuda_bf16.h>
#include <cstdint>

// R9: K0 classify parallelized (was single-thread, ~20us of serial DRAM
// latency); K2 replaced by warp Kogge-Stone scan over chunks (was 128-step
// serial chain on 256 warps). K1/K3 unchanged from R8 (cp.async staging).

#define BB 4
#define LL 4096
#define MM 2048
#define DD 2048
#define EPSV 1e-4f

#define TC 16              // timesteps per chunk
#define NCH (MM / TC)      // 128 chunks
#define DB 512             // channels per block slice
#define THR 128            // threads per block (1 float4 col each)
#define NDS (DD / DB)      // 4 d-slices
#define WPB 8              // K2 warps per block

__device__ float g_p[BB * MM];
__device__ float g_a[BB * MM];
__device__ int   g_bpos[BB * (MM + 1)];
__device__ float g_A[BB * NCH];
__device__ float g_B[BB * NCH * DD];
__device__ float g_Hin[BB * NCH * DD];

__device__ __forceinline__ void cp_async16(void* sdst, const void* gsrc) {
    uint32_t s = (uint32_t)__cvta_generic_to_shared(sdst);
    asm volatile("cp.async.cg.shared.global [%0], [%1], 16;\n"
                 :: "r"(s), "l"(gsrc) : "memory");
}
__device__ __forceinline__ void cp_async_commit_wait() {
    asm volatile("cp.async.commit_group;\n" ::: "memory");
    asm volatile("cp.async.wait_group 0;\n" ::: "memory");
}

// ---------------------------------------------------------------------------
// K0: classify inputs (parallel), then per batch: scan boundary_mask, gather
// p, segment table bpos, per-chunk decay products A.
// ---------------------------------------------------------------------------
__global__ void k0_prep(const uint8_t* s0, const uint8_t* s1,
                        const uint8_t* s2, int ns) {
    const int b = blockIdx.x;
    const int tid = threadIdx.x;              // 1024 threads
    __shared__ int wsum[32];
    __shared__ int s_numB;
    __shared__ int s_pi, s_bi, s_bkind;
    // classification accumulators per small-input: bytebool/wordbool/floatbool
    __shared__ int s_bb[3], s_wb[3], s_fb[3], s_zb[3], s_zw[3];

    const uint8_t* sel[3] = { s0, s1, s2 };

    if (tid < 3) {
        s_bb[tid] = 1; s_wb[tid] = 1; s_fb[tid] = 1;
        s_zb[tid] = 0; s_zw[tid] = 0;
    }
    __syncthreads();

    // 192 threads: 64 words from each of (up to) 3 small inputs, in parallel.
    if (tid < 192) {
        const int arr = tid / 64, i = tid % 64;
        if (arr < ns) {
            const uint32_t v = ((const uint32_t*)sel[arr])[i];
            int wb = (v <= 1u);
            int fb = (v == 0u || v == 0x3F800000u);
            int bb = 1, zb = 0;
#pragma unroll
            for (int k = 0; k < 4; k++) {
                const uint32_t bv = (v >> (8 * k)) & 0xFFu;
                if (bv > 1u) bb = 0;
                if (bv == 0u) zb = 1;
            }
            if (!wb) atomicAnd(&s_wb[arr], 0);
            if (!fb) atomicAnd(&s_fb[arr], 0);
            if (!bb) atomicAnd(&s_bb[arr], 0);
            if (zb)  atomicOr(&s_zb[arr], 1);
            if (v == 0u) atomicOr(&s_zw[arr], 1);
        }
    }
    __syncthreads();

    if (tid == 0) {
        // kind: 0=byte-bool 1=word-bool 2=float-bool 3=prob
        int kind[3], hz[3];
        for (int j = 0; j < ns; j++) {
            if (s_wb[j])      { kind[j] = 1; hz[j] = s_zw[j]; }
            else if (s_fb[j]) { kind[j] = 2; hz[j] = s_zw[j]; }
            else if (s_bb[j]) { kind[j] = 0; hz[j] = s_zb[j]; }
            else              { kind[j] = 3; hz[j] = 0; }
        }
        int pi = -1;
        for (int j = 0; j < ns; j++) if (kind[j] == 3) { pi = j; break; }
        if (pi < 0) pi = 0;
        int bi = -1;
        for (int j = 0; j < ns; j++)
            if (j != pi && kind[j] != 3 && hz[j]) { bi = j; break; }
        if (bi < 0)
            for (int j = 0; j < ns; j++)
                if (j != pi && kind[j] != 3) { bi = j; break; }
        if (bi < 0) bi = (pi == 1) ? 2 : 1;
        s_pi = pi; s_bi = bi; s_bkind = kind[bi];
    }
    __syncthreads();

    const float* prob = (const float*)sel[s_pi];
    const uint8_t* bm = sel[s_bi];
    const int bkind = s_bkind;

    const int l0 = tid * 4;
    int m[4];
    int s = 0;
#pragma unroll
    for (int j = 0; j < 4; j++) {
        const int l = b * LL + l0 + j;
        m[j] = (bkind == 0) ? (bm[l] != 0) : (((const uint32_t*)bm)[l] != 0u);
        s += m[j];
    }

    const int lane = tid & 31, wid = tid >> 5;
    int incl = s;
#pragma unroll
    for (int o = 1; o < 32; o <<= 1) {
        int v = __shfl_up_sync(0xffffffffu, incl, o);
        if (lane >= o) incl += v;
    }
    if (lane == 31) wsum[wid] = incl;
    __syncthreads();
    if (wid == 0) {
        int v = wsum[lane];
#pragma unroll
        for (int o = 1; o < 32; o <<= 1) {
            int u = __shfl_up_sync(0xffffffffu, v, o);
            if (lane >= o) v += u;
        }
        wsum[lane] = v;
        if (lane == 31) s_numB = v;
    }
    __syncthreads();

    const int excl_w = (wid == 0) ? 0 : wsum[wid - 1];
    const int excl_t = excl_w + (incl - s);
    const int numB = s_numB;

    int run = excl_t;
#pragma unroll
    for (int j = 0; j < 4; j++) {
        const int l = l0 + j;
        const int isb = m[j];
        run += isb;
        const int r = isb ? (run - 1) : (numB + (l - run));
        if (r < MM) {
            float p = prob[(size_t)b * LL + l];
            p = fminf(fmaxf(p, EPSV), 1.0f - EPSV);
            g_p[b * MM + r] = p;
            g_a[b * MM + r] = 1.0f - p;
            if (isb) g_bpos[b * (MM + 1) + r] = l;
        }
    }
    for (int r = numB + tid; r <= MM; r += blockDim.x)
        g_bpos[b * (MM + 1) + r] = LL;

    __syncthreads();

    for (int ch = tid; ch < NCH; ch += blockDim.x) {
        float A = 1.0f;
#pragma unroll
        for (int t = 0; t < TC; t++) A *= g_a[b * MM + ch * TC + t];
        g_A[b * NCH + ch] = A;
    }
}

// ---------------------------------------------------------------------------
// K1: cp.async-stage the (TC x DB) tile to smem, chunk-local recurrence with
// h=0 -> per-chunk carry vectors g_B.
// ---------------------------------------------------------------------------
__global__ void __launch_bounds__(THR)
k1_partials(const float* __restrict__ hid) {
    const int ch = blockIdx.x, ds = blockIdx.y, b = blockIdx.z;
    const int tid = threadIdx.x;

    __shared__ float4 tile[TC * THR];          // 32 KB
    __shared__ float sp[TC], sa[TC];
    if (tid < TC) {
        sp[tid] = g_p[b * MM + ch * TC + tid];
        sa[tid] = g_a[b * MM + ch * TC + tid];
    }

    const float4* src =
        (const float4*)(hid + ((size_t)(b * MM + ch * TC)) * DD + ds * DB);
    const int rs = DD / 4;
#pragma unroll
    for (int t = 0; t < TC; t++)
        cp_async16(&tile[t * THR + tid], &src[(size_t)t * rs + tid]);
    cp_async_commit_wait();
    __syncthreads();

    float4 h = make_float4(0.f, 0.f, 0.f, 0.f);
#pragma unroll
    for (int t = 0; t < TC; t++) {
        const float4 x = tile[t * THR + tid];
        const float p = sp[t], a = sa[t];
        h.x = fmaf(a, h.x, p * x.x);
        h.y = fmaf(a, h.y, p * x.y);
        h.z = fmaf(a, h.z, p * x.z);
        h.w = fmaf(a, h.w, p * x.w);
    }
    *((float4*)&g_B[(size_t)(b * NCH + ch) * DD + ds * DB + tid * 4]) = h;
}

// ---------------------------------------------------------------------------
// K2: warp-parallel scan over chunks. One warp per (b,d); 4 chunks per lane
// composed serially, then Kogge-Stone warp scan with the affine combine
// (A2,B2)o(A1,B1) = (A1*A2, A2*B1+B2). Writes exclusive prefixes g_Hin.
// ---------------------------------------------------------------------------
__global__ void __launch_bounds__(WPB * 32)
k2_combine() {
    const int warp = blockIdx.x * WPB + (threadIdx.x >> 5);
    const int lane = threadIdx.x & 31;
    const int b = warp / DD, d = warp % DD;    // block-uniform b (2048 % 8 == 0)

    __shared__ float sA[NCH];
    for (int c = threadIdx.x; c < NCH; c += WPB * 32) sA[c] = g_A[b * NCH + c];
    __syncthreads();

    const int CPT = NCH / 32;                  // 4 chunks per lane
    float a_l[CPT], b_l[CPT];
    float A = 1.f, Bv = 0.f;
#pragma unroll
    for (int k = 0; k < CPT; k++) {
        const int c = lane * CPT + k;
        a_l[k] = sA[c];
        b_l[k] = g_B[(size_t)(b * NCH + c) * DD + d];
        Bv = fmaf(a_l[k], Bv, b_l[k]);         // compose (A,Bv) then (a,b)
        A *= a_l[k];
    }
    float Ai = A, Bi = Bv;                     // inclusive scan over lanes
#pragma unroll
    for (int off = 1; off < 32; off <<= 1) {
        float Ap = __shfl_up_sync(0xffffffffu, Ai, off);
        float Bp = __shfl_up_sync(0xffffffffu, Bi, off);
        if (lane >= off) {
            Bi = fmaf(Ai, Bp, Bi);
            Ai *= Ap;
        }
    }
    float Be = __shfl_up_sync(0xffffffffu, Bi, 1);
    float h = (lane == 0) ? 0.f : Be;          // h before this lane's chunks
#pragma unroll
    for (int k = 0; k < CPT; k++) {
        const int c = lane * CPT + k;
        g_Hin[(size_t)(b * NCH + c) * DD + d] = h;
        h = fmaf(a_l[k], h, b_l[k]);
    }
}

// ---------------------------------------------------------------------------
// K3: cp.async-stage tile, chunk-local scan seeded with g_Hin, scatter each
// state to its output segment [bpos[t], bpos[t+1]).
// ---------------------------------------------------------------------------
__global__ void __launch_bounds__(THR)
k3_final(const float* __restrict__ hid, float* __restrict__ out) {
    const int ch = blockIdx.x, ds = blockIdx.y, b = blockIdx.z;
    const int tid = threadIdx.x;

    __shared__ float4 tile[TC * THR];          // 32 KB
    __shared__ float sp[TC], sa[TC];
    __shared__ int sbp[TC + 1];
    if (tid < TC) {
        sp[tid] = g_p[b * MM + ch * TC + tid];
        sa[tid] = g_a[b * MM + ch * TC + tid];
    }
    if (tid <= TC) sbp[tid] = g_bpos[b * (MM + 1) + ch * TC + tid];

    const float4* src =
        (const float4*)(hid + ((size_t)(b * MM + ch * TC)) * DD + ds * DB);
    const int rs = DD / 4;
#pragma unroll
    for (int t = 0; t < TC; t++)
        cp_async16(&tile[t * THR + tid], &src[(size_t)t * rs + tid]);

    float4 h = *((const float4*)
                 &g_Hin[(size_t)(b * NCH + ch) * DD + ds * DB + tid * 4]);

    cp_async_commit_wait();
    __syncthreads();

    float4* outbase = (float4*)(out + ((size_t)b * LL) * DD + ds * DB + tid * 4);

#pragma unroll
    for (int t = 0; t < TC; t++) {
        const float4 x = tile[t * THR + tid];
        const float p = sp[t], a = sa[t];
        h.x = fmaf(a, h.x, p * x.x);
        h.y = fmaf(a, h.y, p * x.y);
        h.z = fmaf(a, h.z, p * x.z);
        h.w = fmaf(a, h.w, p * x.w);
        const int l0 = sbp[t], l1 = sbp[t + 1];
        for (int l = l0; l < l1; l++) outbase[(size_t)l * rs] = h;
    }
}

// ---------------------------------------------------------------------------
extern "C" void kernel_launch(void* const* d_in, const int* in_sizes, int n_in,
                              void* d_out, int out_size) {
    int hid_i = 0;
    for (int i = 1; i < n_in; i++)
        if (in_sizes[i] > in_sizes[hid_i]) hid_i = i;
    const float* hid = (const float*)d_in[hid_i];

    const void* sm[3] = { nullptr, nullptr, nullptr };
    int ns = 0;
    for (int i = 0; i < n_in && ns < 3; i++)
        if (i != hid_i) sm[ns++] = d_in[i];
    if (ns == 1) { sm[1] = sm[0]; sm[2] = sm[0]; }
    if (ns == 2) { sm[2] = sm[1]; }

    float* out = (float*)d_out;

    k0_prep<<<BB, 1024>>>((const uint8_t*)sm[0], (const uint8_t*)sm[1],
                          (const uint8_t*)sm[2], ns);
    dim3 g(NCH, NDS, BB);
    k1_partials<<<g, THR>>>(hid);
    k2_combine<<<(BB * DD) / WPB, WPB * 32>>>();
    k3_final<<<g, THR>>>(hid, out);
}